// round 2
// baseline (speedup 1.0000x reference)
#include <cuda_runtime.h>
#include <math.h>

// Problem constants
#define BQ   16
#define CDIM 256
#define HW   64
#define NQ   65536          // 16*64*64 queries
#define KCODES 1024
#define ZQ_ELEMS 16777216   // 16*256*64*64

// GEMM tiling
#define MT  128
#define NTC 128
#define KT  16

#define MARGIN 1e-3f
#define CAND_CAP 8

// Scratch (static __device__ globals — allocation-free per harness rules)
__device__ float  g_zf[NQ * CDIM];       // normalized, transposed queries [N, C] (64 MB)
__device__ float  g_wn[KCODES * CDIM];   // normalized codebook [K, C]
__device__ float  g_wn2[KCODES];         // fp32-rounded fp64 sum(wn^2)  (ref's ||wn_k||^2)
__device__ float  g_en[KCODES];          // max(||e_k||, eps)  (denominator)
__device__ float  g_en2[KCODES];         // ||e_k||^2 (fp64->fp32)
__device__ int    g_bi[NQ];              // best index per query (stage1 then final)
__device__ float  g_bd[NQ];              // best dot per query (stage1)
__device__ int    g_ncand[NQ];           // candidate count (may exceed CAND_CAP => overflow)
__device__ int    g_cand[NQ * CAND_CAP]; // candidate code ids
__device__ double g_loss;                // loss accumulator

// ---------------------------------------------------------------------------
// Kernel A: normalize embedding rows (emulating reference arithmetic),
// precompute wn2/en/en2, reset loss accumulator.
// grid 1024, block 256 (one block per code row)
// ---------------------------------------------------------------------------
__global__ void k_prep(const float* __restrict__ emb) {
    int k = blockIdx.x;
    int t = threadIdx.x;
    if (k == 0 && t == 0) g_loss = 0.0;

    __shared__ double red[256];
    float v = emb[k * CDIM + t];
    red[t] = (double)v * (double)v;
    __syncthreads();
    #pragma unroll
    for (int s = 128; s > 0; s >>= 1) {
        if (t < s) red[t] += red[t + s];
        __syncthreads();
    }
    __shared__ float sDen;
    if (t == 0) {
        float n2 = (float)red[0];          // correctly-rounded fp32 sum of squares
        float n  = sqrtf(n2);              // ref: jnp.linalg.norm
        float den = fmaxf(n, 1e-12f);
        g_en[k]  = den;
        g_en2[k] = n2;
        sDen = den;
    }
    __syncthreads();
    float wn = v / sDen;                   // ref: x / max(norm, eps) (division!)
    g_wn[k * CDIM + t] = wn;

    // wn2 = fp32( fp64 sum of wn^2 )  -- the ||wn_k||^2 term in ref's d
    red[t] = (double)wn * (double)wn;
    __syncthreads();
    #pragma unroll
    for (int s = 128; s > 0; s >>= 1) {
        if (t < s) red[t] += red[t + s];
        __syncthreads();
    }
    if (t == 0) g_wn2[k] = (float)red[0];
}

// ---------------------------------------------------------------------------
// Kernel B: L2-normalize z along W (ref-emulating), transpose -> zf [N, C]
// grid 1024 = B*H blocks, 256 threads.
// ---------------------------------------------------------------------------
__global__ void k_znorm(const float* __restrict__ z) {
    __shared__ float tile[64][65];   // [c_local][w], padded
    __shared__ float den[64];
    int bh = blockIdx.x;
    int b = bh >> 6, h = bh & 63;
    int t = threadIdx.x;
    long n0 = (long)bh * 64;

    for (int c0 = 0; c0 < CDIM; c0 += 64) {
        for (int i = t; i < 4096; i += 256) {
            int r = i >> 6, w = i & 63;
            tile[r][w] = z[(((long)b * CDIM + (c0 + r)) * HW + h) * HW + w];
        }
        __syncthreads();
        if (t < 64) {
            double s = 0.0;
            #pragma unroll
            for (int w = 0; w < 64; w++) { double v = (double)tile[t][w]; s += v * v; }
            float n = sqrtf((float)s);                 // fp32 round of exact sumsq, then sqrtf
            den[t] = fmaxf(n, 1e-12f);
        }
        __syncthreads();
        // transposed, normalized write (division, as in reference)
        for (int i = t; i < 4096; i += 256) {
            int w = i >> 6, cc = i & 63;
            g_zf[(n0 + w) * CDIM + c0 + cc] = tile[cc][w] / den[cc];
        }
        __syncthreads();
    }
}

// ---------------------------------------------------------------------------
// Kernel C: fused fp32 GEMM (D = zf * wn^T) + per-row argmax + candidate
// collection within MARGIN of running best. 512 blocks x 256 threads.
// ---------------------------------------------------------------------------
__global__ void __launch_bounds__(256, 2) k_gemm_argmax() {
    __shared__ float As[2][KT][MT];
    __shared__ float Bs[2][KT][NTC];
    __shared__ float s_bv[MT];
    __shared__ int   s_bi[MT];
    __shared__ int   s_cnt[MT];
    __shared__ int   s_cand[MT][CAND_CAP];

    int t  = threadIdx.x;
    int tx = t & 15;          // code-dim thread coord
    int ty = t >> 4;          // query-dim thread coord
    int n0 = blockIdx.x * MT;

    if (t < MT) { s_bv[t] = -3.0e38f; s_bi[t] = 0; s_cnt[t] = 0; }
    __syncthreads();

    const float* Abase = g_zf + (long)n0 * CDIM;

    int lr0 = t >> 2,         lc0 = (t & 3) * 4;
    int lr1 = (t + 256) >> 2, lc1 = ((t + 256) & 3) * 4;

    for (int ch = 0; ch < 8; ch++) {
        int code0 = ch * NTC;
        const float* Bbase = g_wn + (long)code0 * CDIM;

        float acc[8][8];
        #pragma unroll
        for (int i = 0; i < 8; i++)
            #pragma unroll
            for (int j = 0; j < 8; j++) acc[i][j] = 0.0f;

        // prologue: k-tile 0 -> buffer 0
        {
            float4 a0 = *(const float4*)(Abase + (long)lr0 * CDIM + lc0);
            float4 a1 = *(const float4*)(Abase + (long)lr1 * CDIM + lc1);
            float4 b0 = *(const float4*)(Bbase + (long)lr0 * CDIM + lc0);
            float4 b1 = *(const float4*)(Bbase + (long)lr1 * CDIM + lc1);
            As[0][lc0 + 0][lr0] = a0.x; As[0][lc0 + 1][lr0] = a0.y;
            As[0][lc0 + 2][lr0] = a0.z; As[0][lc0 + 3][lr0] = a0.w;
            As[0][lc1 + 0][lr1] = a1.x; As[0][lc1 + 1][lr1] = a1.y;
            As[0][lc1 + 2][lr1] = a1.z; As[0][lc1 + 3][lr1] = a1.w;
            Bs[0][lc0 + 0][lr0] = b0.x; Bs[0][lc0 + 1][lr0] = b0.y;
            Bs[0][lc0 + 2][lr0] = b0.z; Bs[0][lc0 + 3][lr0] = b0.w;
            Bs[0][lc1 + 0][lr1] = b1.x; Bs[0][lc1 + 1][lr1] = b1.y;
            Bs[0][lc1 + 2][lr1] = b1.z; Bs[0][lc1 + 3][lr1] = b1.w;
        }
        __syncthreads();

        for (int kt = 0; kt < CDIM / KT; kt++) {
            int cur = kt & 1;
            float4 na0, na1, nb0, nb1;
            if (kt < CDIM / KT - 1) {
                int c0 = (kt + 1) * KT;
                na0 = *(const float4*)(Abase + (long)lr0 * CDIM + c0 + lc0);
                na1 = *(const float4*)(Abase + (long)lr1 * CDIM + c0 + lc1);
                nb0 = *(const float4*)(Bbase + (long)lr0 * CDIM + c0 + lc0);
                nb1 = *(const float4*)(Bbase + (long)lr1 * CDIM + c0 + lc1);
            }
            #pragma unroll
            for (int k = 0; k < KT; k++) {
                float4 af0 = *(const float4*)&As[cur][k][ty * 8];
                float4 af1 = *(const float4*)&As[cur][k][ty * 8 + 4];
                float4 bf0 = *(const float4*)&Bs[cur][k][tx * 8];
                float4 bf1 = *(const float4*)&Bs[cur][k][tx * 8 + 4];
                float a[8]  = {af0.x, af0.y, af0.z, af0.w, af1.x, af1.y, af1.z, af1.w};
                float bb[8] = {bf0.x, bf0.y, bf0.z, bf0.w, bf1.x, bf1.y, bf1.z, bf1.w};
                #pragma unroll
                for (int i = 0; i < 8; i++)
                    #pragma unroll
                    for (int j = 0; j < 8; j++)
                        acc[i][j] = fmaf(a[i], bb[j], acc[i][j]);
            }
            if (kt < CDIM / KT - 1) {
                int nxt = cur ^ 1;
                As[nxt][lc0 + 0][lr0] = na0.x; As[nxt][lc0 + 1][lr0] = na0.y;
                As[nxt][lc0 + 2][lr0] = na0.z; As[nxt][lc0 + 3][lr0] = na0.w;
                As[nxt][lc1 + 0][lr1] = na1.x; As[nxt][lc1 + 1][lr1] = na1.y;
                As[nxt][lc1 + 2][lr1] = na1.z; As[nxt][lc1 + 3][lr1] = na1.w;
                Bs[nxt][lc0 + 0][lr0] = nb0.x; Bs[nxt][lc0 + 1][lr0] = nb0.y;
                Bs[nxt][lc0 + 2][lr0] = nb0.z; Bs[nxt][lc0 + 3][lr0] = nb0.w;
                Bs[nxt][lc1 + 0][lr1] = nb1.x; Bs[nxt][lc1 + 1][lr1] = nb1.y;
                Bs[nxt][lc1 + 2][lr1] = nb1.z; Bs[nxt][lc1 + 3][lr1] = nb1.w;
            }
            __syncthreads();
        }

        // chunk argmax update
        #pragma unroll
        for (int i = 0; i < 8; i++) {
            float bv = acc[i][0];
            int   bj = 0;
            #pragma unroll
            for (int j = 1; j < 8; j++)
                if (acc[i][j] > bv) { bv = acc[i][j]; bj = j; }
            int bc = code0 + tx * 8 + bj;
            #pragma unroll
            for (int off = 8; off > 0; off >>= 1) {
                float ov = __shfl_xor_sync(0xFFFFFFFFu, bv, off, 16);
                int   oc = __shfl_xor_sync(0xFFFFFFFFu, bc, off, 16);
                if (ov > bv || (ov == bv && oc < bc)) { bv = ov; bc = oc; }
            }
            if (tx == 0) {
                int row = ty * 8 + i;
                if (bv > s_bv[row]) { s_bv[row] = bv; s_bi[row] = bc; }
            }
        }
        __syncthreads();

        // candidate collection vs running best (superset of final-margin set)
        #pragma unroll
        for (int i = 0; i < 8; i++) {
            int row = ty * 8 + i;
            float thr = s_bv[row] - MARGIN;
            #pragma unroll
            for (int j = 0; j < 8; j++) {
                if (acc[i][j] >= thr) {
                    int pos = atomicAdd(&s_cnt[row], 1);
                    if (pos < CAND_CAP) s_cand[row][pos] = code0 + tx * 8 + j;
                }
            }
        }
        __syncthreads();
    }

    if (t < MT) {
        int n = n0 + t;
        g_bi[n] = s_bi[t];
        g_bd[n] = s_bv[t];
        int cnt = s_cnt[t];
        g_ncand[n] = cnt;
        int m = cnt < CAND_CAP ? cnt : CAND_CAP;
        for (int c = 0; c < m; c++) g_cand[n * CAND_CAP + c] = s_cand[t][c];
    }
}

// ---------------------------------------------------------------------------
// Kernel C2: exact re-ranking of candidates, emulating reference arithmetic.
// One warp per query. d̂_k = fp32( fp32(zf2f + wn2f[k]) - 2*fp32(dot_fp64) ),
// ties -> lowest k. Also accumulates loss partial with the FINAL winner.
// ---------------------------------------------------------------------------
__global__ void k_refine(float* __restrict__ out_idx) {
    int warp = (blockIdx.x * blockDim.x + threadIdx.x) >> 5;
    int lane = threadIdx.x & 31;
    __shared__ double s_loss;
    if (threadIdx.x == 0) s_loss = 0.0;
    __syncthreads();

    double myloss = 0.0;
    if (warp < NQ) {
        int n = warp;
        int cnt = g_ncand[n];
        int bi; float bd;
        if (cnt <= 1) {
            bi = g_bi[n]; bd = g_bd[n];
        } else {
            float zr[8];
            #pragma unroll
            for (int m = 0; m < 8; m++) zr[m] = g_zf[(long)n * CDIM + lane + 32 * m];
            double z2 = 0.0;
            #pragma unroll
            for (int m = 0; m < 8; m++) z2 += (double)zr[m] * (double)zr[m];
            #pragma unroll
            for (int off = 16; off > 0; off >>= 1)
                z2 += __shfl_xor_sync(0xFFFFFFFFu, z2, off);
            float zf2f = (float)z2;

            bool overflow = (cnt > CAND_CAP);
            int ncand = overflow ? KCODES : cnt;
            float dmin = 3.4e38f; int kmin = 0x7FFFFFFF; float bestdot = 0.0f;
            for (int ci = 0; ci < ncand; ci++) {
                int k = overflow ? ci : g_cand[n * CAND_CAP + ci];
                double dot = 0.0;
                const float* wrow = g_wn + (long)k * CDIM;
                #pragma unroll
                for (int m = 0; m < 8; m++)
                    dot += (double)zr[m] * (double)wrow[lane + 32 * m];
                #pragma unroll
                for (int off = 16; off > 0; off >>= 1)
                    dot += __shfl_xor_sync(0xFFFFFFFFu, dot, off);
                float dotf = (float)dot;
                float tsum = zf2f + g_wn2[k];
                float d = tsum - 2.0f * dotf;
                if (d < dmin || (d == dmin && k < kmin)) {
                    dmin = d; kmin = k; bestdot = dotf;
                }
            }
            bi = kmin; bd = bestdot;
        }
        if (lane == 0) {
            g_bi[n] = bi;
            out_idx[n] = (float)bi;
            myloss = (double)g_en2[bi] - 2.0 * (double)bd * (double)g_en[bi];
            atomicAdd(&s_loss, myloss);
        }
    }
    __syncthreads();
    if (threadIdx.x == 0) atomicAdd(&g_loss, s_loss);
}

// ---------------------------------------------------------------------------
// Kernel D: gather z_q = embedding[idx], write transposed back to [B,C,H,W]
// ---------------------------------------------------------------------------
__global__ void k_gather(const float* __restrict__ emb, float* __restrict__ out) {
    __shared__ int   sIdx[64];
    __shared__ float es[64][129];
    int bh = blockIdx.x;
    int b = bh >> 6, h = bh & 63;
    int t = threadIdx.x;
    long n0 = (long)bh * 64;

    if (t < 64) sIdx[t] = g_bi[n0 + t];
    __syncthreads();

    for (int c0 = 0; c0 < CDIM; c0 += 128) {
        for (int i = t; i < 64 * 128; i += 256) {
            int s = i >> 7, cc = i & 127;
            es[s][cc] = emb[(long)sIdx[s] * CDIM + c0 + cc];
        }
        __syncthreads();
        for (int i = t; i < 64 * 128; i += 256) {
            int cc = i >> 6, w = i & 63;
            out[(((long)b * CDIM + (c0 + cc)) * HW + h) * HW + w] = es[w][cc];
        }
        __syncthreads();
    }
}

// ---------------------------------------------------------------------------
// Kernel E: finalize loss. Sum_n ||zf_n||^2 == 262144 (unit-norm W-rows).
// ---------------------------------------------------------------------------
__global__ void k_loss(float* __restrict__ out_loss) {
    double S = g_loss + 262144.0;
    out_loss[0] = (float)(1.25 * S / (double)ZQ_ELEMS);
}

// ---------------------------------------------------------------------------
extern "C" void kernel_launch(void* const* d_in, const int* in_sizes, int n_in,
                              void* d_out, int out_size) {
    const float* z   = (const float*)d_in[0];   // [16,256,64,64]
    const float* emb = (const float*)d_in[1];   // [1024,256]
    float* out = (float*)d_out;                 // [z_q | idx | loss]

    k_prep<<<KCODES, 256>>>(emb);
    k_znorm<<<BQ * HW, 256>>>(z);
    k_gemm_argmax<<<NQ / MT, 256>>>();
    k_refine<<<NQ / 8, 256>>>(out + ZQ_ELEMS);
    k_gather<<<BQ * HW, 256>>>(emb, out);
    k_loss<<<1, 1>>>(out + ZQ_ELEMS + NQ);
}